// round 15
// baseline (speedup 1.0000x reference)
#include <cuda_runtime.h>
#include <cuda_bf16.h>
#include <cstdint>

#define BATCH  4096
#define NREL   128
#define EMB    256
#define KDIM   512
#define NSEG   8

// ---------------- device globals ----------------
// B pre-packed: [2 ntiles][8 segs][ w2-tile 8K | w1-tile 8K ]  (256 KB)
__device__ __align__(128) __nv_bfloat16 g_Bs[NREL * 1024];
__device__ __align__(16) float g_const[NREL];

// ---------------- helpers ----------------
__device__ __forceinline__ uint32_t smem_u32(const void* p) {
    uint32_t a;
    asm("{ .reg .u64 t; cvta.to.shared.u64 t, %1; cvt.u32.u64 %0, t; }" : "=r"(a) : "l"(p));
    return a;
}
__device__ __forceinline__ void ldsm_x4(uint32_t& r0, uint32_t& r1, uint32_t& r2, uint32_t& r3,
                                        uint32_t addr) {
    asm volatile("ldmatrix.sync.aligned.m8n8.x4.shared.b16 {%0,%1,%2,%3}, [%4];"
                 : "=r"(r0), "=r"(r1), "=r"(r2), "=r"(r3) : "r"(addr));
}
__device__ __forceinline__ void mma16816(float* d, const uint32_t* a, uint32_t b0, uint32_t b1) {
    asm volatile(
        "mma.sync.aligned.m16n8k16.row.col.f32.bf16.bf16.f32 "
        "{%0,%1,%2,%3}, {%4,%5,%6,%7}, {%8,%9}, {%0,%1,%2,%3};"
        : "+f"(d[0]), "+f"(d[1]), "+f"(d[2]), "+f"(d[3])
        : "r"(a[0]), "r"(a[1]), "r"(a[2]), "r"(a[3]), "r"(b0), "r"(b1));
}
#define MBAR_INIT(addr, cnt) \
    asm volatile("mbarrier.init.shared.b64 [%0], %1;" :: "r"(addr), "r"((uint32_t)(cnt)) : "memory")
#define MBAR_EXPECT_TX(addr, bytes) \
    asm volatile("mbarrier.arrive.expect_tx.shared.b64 _, [%0], %1;" :: "r"(addr), "r"((uint32_t)(bytes)) : "memory")
#define MBAR_WAIT(addr, par) do { \
    uint32_t _m = (addr); uint32_t _p = (par); uint32_t _d; \
    asm volatile("{\n\t.reg .pred p;\n\tmbarrier.try_wait.parity.acquire.cta.shared::cta.b64 p, [%1], %2;\n\tselp.b32 %0, 1, 0, p;\n\t}" \
        : "=r"(_d) : "r"(_m), "r"(_p) : "memory"); \
    if (!_d) { \
        asm volatile("{\n\t.reg .pred P1;\n\tWL_%=: \n\tmbarrier.try_wait.parity.acquire.cta.shared::cta.b64 P1, [%0], %1, 0x989680;\n\t@P1 bra.uni WD_%=;\n\tbra.uni WL_%=;\n\tWD_%=: \n\t}" \
            :: "r"(_m), "r"(_p) : "memory"); \
    } } while (0)
#define CP_BULK(dst, src, sz, mbar) \
    asm volatile("cp.async.bulk.shared::cta.global.mbarrier::complete_tx::bytes [%0], [%1], %2, [%3];" \
        :: "r"(dst), "l"(src), "r"((uint32_t)(sz)), "r"(mbar) : "memory")
#define FENCE_ASYNC() asm volatile("fence.proxy.async.shared::cta;" ::: "memory")

#define SWZ(bo) ((bo) ^ (((bo) >> 3) & 0x70))

// ---------------- prep: pack B + const + zero out (one block per relation) ----------------
__global__ void prep_B(const float* __restrict__ mus,
                       const float* __restrict__ sigmas,
                       const float* __restrict__ priors,
                       float* __restrict__ out) {
    asm volatile("griddepcontrol.launch_dependents;");

    const int r = blockIdx.x;          // 0..127
    const int t = threadIdx.x;         // 0..255
    const int nt  = r >> 6;
    const int rin = r & 63;
    char* base = reinterpret_cast<char*>(g_Bs) + (size_t)nt * 8 * 16384;

    // zero out: 4096x128 floats, 128 blocks x 256 thr x 16 floats
    {
        float4* o = reinterpret_cast<float4*>(out) + ((size_t)r * 256 + t) * 4;
        const float4 z = make_float4(0.f, 0.f, 0.f, 0.f);
        o[0] = z; o[1] = z; o[2] = z; o[3] = z;
    }

    float part = 0.0f;
    #pragma unroll
    for (int i = 0; i < 2; i++) {
        const int k = t + i * 256;     // 0..511
        const float s    = sigmas[r * KDIM + k];
        const float mu   = mus[r * KDIM + k];
        const float inv2 = 1.0f / (s * s);
        const int seg = k >> 6;
        const uint32_t off = SWZ((uint32_t)(rin * 128 + (k & 63) * 2));
        *reinterpret_cast<__nv_bfloat16*>(base + (size_t)seg * 16384 + off)
            = __float2bfloat16(-0.5f * inv2);        // w2 <-> x^2
        *reinterpret_cast<__nv_bfloat16*>(base + (size_t)seg * 16384 + 8192 + off)
            = __float2bfloat16(mu * inv2);           // w1 <-> x
        part += -0.5f * mu * mu * inv2 - logf(s) - 0.9189385332046727f;
    }

    __shared__ float red[8];
    #pragma unroll
    for (int off = 16; off > 0; off >>= 1)
        part += __shfl_down_sync(0xffffffffu, part, off);
    if ((t & 31) == 0) red[t >> 5] = part;
    __syncthreads();
    if (t < 8) {
        float v = red[t];
        #pragma unroll
        for (int off = 4; off > 0; off >>= 1)
            v += __shfl_down_sync(0x000000ffu, v, off);
        if (t == 0) g_const[r] = v + priors[r] * (float)KDIM;
    }
}

// ---------------- main ----------------
// Grid 256 = 64 mt x 2 nt x 2 khalf. CTA 64x64, 512 thr = 4 groups x 4 warps
// (warp tile 32x32). Group g handles ONE segment: sg = khalf*4 + g.
//   A: [4 groups][x^2 8K | x 8K] = 64 KB (loaded once)
//   B: [4 groups][8 KB slot]     = 32 KB (w2 first, w1 reissued into same slot)
// smem 96 KB -> 2 CTAs/SM, 32 warps/SM. Split-K partials atomically added to out.
#define SMB_OFF     65536
#define MBAR_OFF    (SMB_OFF + 4 * 8192)         // 98304
#define SMEM_TOTAL  (MBAR_OFF + 64)              // 98368

__global__ __launch_bounds__(512, 2)
void nb_mma(const float* __restrict__ sbjs,
            const float* __restrict__ objs,
            float* __restrict__ out) {
    extern __shared__ char smem[];
    const uint32_t sb = smem_u32(smem);

    const int tid   = threadIdx.x;
    const int lane  = tid & 31;
    const int wid   = tid >> 5;             // 0..15
    const int group = wid >> 2;             // 0..3
    const int gw    = wid & 3;
    const int wm    = gw & 1;               // m offset 32
    const int wn    = gw >> 1;              // n offset 32
    const int gtid  = tid & 127;
    const int mtile = blockIdx.x >> 2;      // 0..63
    const int ntile = (blockIdx.x >> 1) & 1;
    const int kh    = blockIdx.x & 1;       // K half
    const int sg    = kh * 4 + group;       // this group's segment 0..7

    if (tid == 0) {
        #pragma unroll
        for (int s = 0; s < 4; s++) MBAR_INIT(sb + MBAR_OFF + s * 8, 1);
    }
    __syncthreads();

    const char* bSrc = reinterpret_cast<const char*>(g_Bs) + (size_t)ntile * 8 * 16384;

    // initial B issue: w2 chunk of each group's segment (gated on prep_B)
    if (tid == 0) {
        asm volatile("griddepcontrol.wait;");
        #pragma unroll
        for (int g = 0; g < 4; g++) {
            const uint32_t mb = sb + MBAR_OFF + g * 8;
            MBAR_EXPECT_TX(mb, 8192);
            CP_BULK(sb + SMB_OFF + g * 8192, bSrc + (size_t)(kh * 4 + g) * 16384, 8192, mb);
        }
    }

    // ---- A load: group's single segment (128 threads, 4 virtual passes) ----
    {
        char* dst = smem + (size_t)group * 16384;
        #pragma unroll
        for (int p = 0; p < 4; p++) {
            const int vt   = gtid + p * 128;     // 0..511
            const int arow = vt >> 3;            // 0..63
            const int kq   = (vt & 7) * 8;       // 0..56
            const int kg   = sg * 64 + kq;
            const float* src = (kg < EMB)
                ? sbjs + (size_t)(mtile * 64 + arow) * EMB + kg
                : objs + (size_t)(mtile * 64 + arow) * EMB + (kg - EMB);
            const float4 v0 = reinterpret_cast<const float4*>(src)[0];
            const float4 v1 = reinterpret_cast<const float4*>(src)[1];
            const uint32_t aOff = SWZ((uint32_t)(arow * 128 + kq * 2));
            __nv_bfloat162 q0 = __floats2bfloat162_rn(v0.x * v0.x, v0.y * v0.y);
            __nv_bfloat162 q1 = __floats2bfloat162_rn(v0.z * v0.z, v0.w * v0.w);
            __nv_bfloat162 q2 = __floats2bfloat162_rn(v1.x * v1.x, v1.y * v1.y);
            __nv_bfloat162 q3 = __floats2bfloat162_rn(v1.z * v1.z, v1.w * v1.w);
            __nv_bfloat162 r0 = __floats2bfloat162_rn(v0.x, v0.y);
            __nv_bfloat162 r1 = __floats2bfloat162_rn(v0.z, v0.w);
            __nv_bfloat162 r2 = __floats2bfloat162_rn(v1.x, v1.y);
            __nv_bfloat162 r3 = __floats2bfloat162_rn(v1.z, v1.w);
            uint4 uq, ur;
            uq.x = *reinterpret_cast<uint32_t*>(&q0); uq.y = *reinterpret_cast<uint32_t*>(&q1);
            uq.z = *reinterpret_cast<uint32_t*>(&q2); uq.w = *reinterpret_cast<uint32_t*>(&q3);
            ur.x = *reinterpret_cast<uint32_t*>(&r0); ur.y = *reinterpret_cast<uint32_t*>(&r1);
            ur.z = *reinterpret_cast<uint32_t*>(&r2); ur.w = *reinterpret_cast<uint32_t*>(&r3);
            *reinterpret_cast<uint4*>(dst + aOff)        = uq;   // x^2 tile
            *reinterpret_cast<uint4*>(dst + 8192 + aOff) = ur;   // x tile
        }
    }
    #define BARG() asm volatile("bar.sync %0, %1;" :: "r"(group + 1), "r"(128) : "memory")

    // ---- compute mappings: warp tile 32x32 ----
    uint32_t aRowOff[2], aXorr[2];
    #pragma unroll
    for (int mf = 0; mf < 2; mf++) {
        const int row = wm * 32 + mf * 16 + (lane & 15);
        aRowOff[mf] = (uint32_t)(row * 128);
        aXorr[mf]   = (uint32_t)((row & 7) << 4);
    }
    const uint32_t aBlk = (uint32_t)((lane >> 4) * 16);
    uint32_t bRowOff[2], bXorr[2];
    #pragma unroll
    for (int bf = 0; bf < 2; bf++) {
        const int nrow = wn * 32 + bf * 16 + ((lane >> 4) * 8) + (lane & 7);
        bRowOff[bf] = (uint32_t)(nrow * 128);
        bXorr[bf]   = (uint32_t)((nrow & 7) << 4);
    }
    const uint32_t bBlk = (uint32_t)(((lane >> 3) & 1) * 16);

    float acc[2][4][4];
    #pragma unroll
    for (int i = 0; i < 2; i++)
        #pragma unroll
        for (int j = 0; j < 4; j++)
            #pragma unroll
            for (int k = 0; k < 4; k++) acc[i][j][k] = 0.0f;

    const uint32_t aStage = sb + (uint32_t)group * 16384;
    const uint32_t bSlot  = sb + SMB_OFF + (uint32_t)group * 8192;

    auto compute_half = [&](uint32_t aB) {
        #pragma unroll
        for (int ks = 0; ks < 4; ks++) {
            const uint32_t kcol = (uint32_t)(ks * 32);
            uint32_t a0[4], a1[4], b0[4], b1[4];
            ldsm_x4(a0[0], a0[1], a0[2], a0[3], aB + aRowOff[0] + ((kcol + aBlk) ^ aXorr[0]));
            ldsm_x4(a1[0], a1[1], a1[2], a1[3], aB + aRowOff[1] + ((kcol + aBlk) ^ aXorr[1]));
            ldsm_x4(b0[0], b0[1], b0[2], b0[3], bSlot + bRowOff[0] + ((kcol + bBlk) ^ bXorr[0]));
            ldsm_x4(b1[0], b1[1], b1[2], b1[3], bSlot + bRowOff[1] + ((kcol + bBlk) ^ bXorr[1]));
            mma16816(acc[0][0], a0, b0[0], b0[1]);
            mma16816(acc[0][1], a0, b0[2], b0[3]);
            mma16816(acc[0][2], a0, b1[0], b1[1]);
            mma16816(acc[0][3], a0, b1[2], b1[3]);
            mma16816(acc[1][0], a1, b0[0], b0[1]);
            mma16816(acc[1][1], a1, b0[2], b0[3]);
            mma16816(acc[1][2], a1, b1[0], b1[1]);
            mma16816(acc[1][3], a1, b1[2], b1[3]);
        }
    };

    // ---- group flow ----
    BARG();                                  // A tile of this group resident
    MBAR_WAIT(sb + MBAR_OFF + group * 8, 0); // w2 resident
    compute_half(aStage);                    // x^2 * w2
    BARG();                                  // all group warps done reading w2
    if (gtid == 0) {
        FENCE_ASYNC();                       // order prior smem reads vs async write
        const uint32_t mb = sb + MBAR_OFF + group * 8;
        MBAR_EXPECT_TX(mb, 8192);
        CP_BULK(bSlot, bSrc + (size_t)sg * 16384 + 8192, 8192, mb);  // w1
    }
    MBAR_WAIT(sb + MBAR_OFF + group * 8, 1); // w1 resident
    compute_half(aStage + 8192);             // x * w1
    BARG();                                  // group done reading its A region

    // ---- partials -> smem (reuse this group's A region: 64x64 fp32 = 16 KB) ----
    {
        float* red = reinterpret_cast<float*>(smem + (size_t)group * 16384);
        #pragma unroll
        for (int mf = 0; mf < 2; mf++) {
            #pragma unroll
            for (int nf = 0; nf < 4; nf++) {
                const int row0 = wm * 32 + mf * 16 + (lane >> 2);
                const int col0 = wn * 32 + nf * 8 + (lane & 3) * 2;
                float2 lo, hi;
                lo.x = acc[mf][nf][0]; lo.y = acc[mf][nf][1];
                hi.x = acc[mf][nf][2]; hi.y = acc[mf][nf][3];
                *reinterpret_cast<float2*>(&red[row0 * 64 + col0])       = lo;
                *reinterpret_cast<float2*>(&red[(row0 + 8) * 64 + col0]) = hi;
            }
        }
    }
    __syncthreads();

    // ---- reduce 4 group partials (+const on kh==0) -> atomicAdd to out ----
    {
        asm volatile("griddepcontrol.wait;");   // out is zeroed by prep_B
        const int row = tid >> 3;               // 0..63
        const int c8  = (tid & 7) * 8;          // 0..56
        float s[8];
        #pragma unroll
        for (int j = 0; j < 8; j++) s[j] = 0.0f;
        #pragma unroll
        for (int g = 0; g < 4; g++) {
            const float* rg = reinterpret_cast<const float*>(smem + (size_t)g * 16384);
            const float4 f0 = *reinterpret_cast<const float4*>(&rg[row * 64 + c8]);
            const float4 f1 = *reinterpret_cast<const float4*>(&rg[row * 64 + c8 + 4]);
            s[0] += f0.x; s[1] += f0.y; s[2] += f0.z; s[3] += f0.w;
            s[4] += f1.x; s[5] += f1.y; s[6] += f1.z; s[7] += f1.w;
        }
        if (kh == 0) {
            #pragma unroll
            for (int j = 0; j < 8; j++) s[j] += g_const[ntile * 64 + c8 + j];
        }
        float* o = &out[(size_t)(mtile * 64 + row) * NREL + ntile * 64 + c8];
        #pragma unroll
        for (int j = 0; j < 8; j++) atomicAdd(o + j, s[j]);
    }
}

extern "C" void kernel_launch(void* const* d_in, const int* in_sizes, int n_in,
                              void* d_out, int out_size) {
    const float* sbjs   = (const float*)d_in[0];
    const float* objs   = (const float*)d_in[1];
    const float* mus    = (const float*)d_in[2];
    const float* sigmas = (const float*)d_in[3];
    const float* priors = (const float*)d_in[4];
    float* out = (float*)d_out;

    cudaFuncSetAttribute(nb_mma, cudaFuncAttributeMaxDynamicSharedMemorySize, SMEM_TOTAL);

    prep_B<<<NREL, 256>>>(mus, sigmas, priors, out);

    cudaLaunchConfig_t cfg = {};
    cfg.gridDim  = dim3(256, 1, 1);
    cfg.blockDim = dim3(512, 1, 1);
    cfg.dynamicSmemBytes = SMEM_TOTAL;
    cfg.stream = 0;
    cudaLaunchAttribute attrs[1];
    attrs[0].id = cudaLaunchAttributeProgrammaticStreamSerialization;
    attrs[0].val.programmaticStreamSerializationAllowed = 1;
    cfg.attrs = attrs;
    cfg.numAttrs = 1;
    cudaError_t e = cudaLaunchKernelEx(&cfg, nb_mma, sbjs, objs, out);
    if (e != cudaSuccess) {
        (void)cudaGetLastError();
        nb_mma<<<256, 512, SMEM_TOTAL>>>(sbjs, objs, out);
    }
    (void)in_sizes; (void)n_in; (void)out_size;
}